// round 1
// baseline (speedup 1.0000x reference)
#include <cuda_runtime.h>
#include <math.h>

#define B_  32
#define S_  512
#define D_  9
#define E_  256
#define F_  1024
#define L_  4
#define C_  10
#define H_  8
#define HD_ 32
#define M_  (B_*S_)          // 16384 rows
#define QKV_LD 768

// ---------------- scratch (static __device__, no allocs) ----------------
__device__ float g_x  [M_*E_];       // activations [16384,256]
__device__ float g_qkv[M_*3*E_];     // qkv          [16384,768]
__device__ float g_y  [M_*E_];       // proj/ffn2 out
__device__ float g_h  [M_*F_];       // ffn hidden   [16384,1024]

// ---------------- reductions ----------------
__device__ __forceinline__ float warpSum(float v) {
    #pragma unroll
    for (int o = 16; o > 0; o >>= 1) v += __shfl_xor_sync(0xffffffffu, v, o);
    return v;
}
__device__ __forceinline__ float warpMax(float v) {
    #pragma unroll
    for (int o = 16; o > 0; o >>= 1) v = fmaxf(v, __shfl_xor_sync(0xffffffffu, v, o));
    return v;
}
// blockDim.x == 256 (8 warps)
__device__ float blockSum(float v, float* red) {
    int lane = threadIdx.x & 31, wid = threadIdx.x >> 5;
    v = warpSum(v);
    if (lane == 0) red[wid] = v;
    __syncthreads();
    if (wid == 0) {
        float x = (lane < 8) ? red[lane] : 0.f;
        x = warpSum(x);
        if (lane == 0) red[0] = x;
    }
    __syncthreads();
    float r = red[0];
    __syncthreads();
    return r;
}
__device__ float blockMax(float v, float* red) {
    int lane = threadIdx.x & 31, wid = threadIdx.x >> 5;
    v = warpMax(v);
    if (lane == 0) red[wid] = v;
    __syncthreads();
    if (wid == 0) {
        float x = (lane < 8) ? red[lane] : -1e30f;
        x = warpMax(x);
        if (lane == 0) red[0] = x;
    }
    __syncthreads();
    float r = red[0];
    __syncthreads();
    return r;
}

// ---------------- embed + posenc ----------------
__global__ void embed_kernel(const float* __restrict__ src,
                             const float* __restrict__ embW,
                             const float* __restrict__ embb) {
    int m = blockIdx.x;          // 0..16383
    int e = threadIdx.x;         // 0..255
    __shared__ float sv[D_];
    if (e < D_) sv[e] = src[m*D_ + e];
    __syncthreads();
    float acc = 0.f;
    #pragma unroll
    for (int d = 0; d < D_; d++) acc += sv[d] * embW[e*D_ + d];
    acc = (acc + embb[e]) * 16.0f;            // sqrt(256)
    int s  = m & (S_-1);
    int j2 = (e >> 1) * 2;
    const float c = -9.210340371976184f / (float)E_;   // -ln(10000)/E
    float ang = (float)s * expf((float)j2 * c);
    float pe  = (e & 1) ? cosf(ang) : sinf(ang);
    g_x[(size_t)m*E_ + e] = acc + pe;
}

// ---------------- SGEMM: C[m,n] = sum_k A[m,k]*B[n,k] + bias[n] (opt relu) ----------------
// BM=BN=128, BK=8, 256 threads, 8x8 per thread. Dims assumed divisible.
__global__ __launch_bounds__(256)
void gemm_nt(const float* __restrict__ A, int lda,
             const float* __restrict__ B,        // [N,K], ldb=K
             const float* __restrict__ bias,
             float* __restrict__ C,              // [M,N], ldc=N
             int N, int K, int doRelu) {
    __shared__ float As[8][132];
    __shared__ float Bs[8][132];
    int tid = threadIdx.x;
    int tx = tid & 15, ty = tid >> 4;
    int bm = blockIdx.y * 128, bn = blockIdx.x * 128;

    int lrow = tid >> 1;           // 0..127
    int lk   = (tid & 1) * 4;      // 0 or 4
    const float* Ap = A + (size_t)(bm + lrow) * lda + lk;
    const float* Bp = B + (size_t)(bn + lrow) * K   + lk;

    float acc[8][8];
    #pragma unroll
    for (int i = 0; i < 8; i++)
        #pragma unroll
        for (int j = 0; j < 8; j++) acc[i][j] = 0.f;

    for (int k0 = 0; k0 < K; k0 += 8) {
        float4 av = *(const float4*)(Ap + k0);
        float4 bv = *(const float4*)(Bp + k0);
        __syncthreads();
        As[lk+0][lrow] = av.x; As[lk+1][lrow] = av.y;
        As[lk+2][lrow] = av.z; As[lk+3][lrow] = av.w;
        Bs[lk+0][lrow] = bv.x; Bs[lk+1][lrow] = bv.y;
        Bs[lk+2][lrow] = bv.z; Bs[lk+3][lrow] = bv.w;
        __syncthreads();
        #pragma unroll
        for (int k = 0; k < 8; k++) {
            float4 a0 = *(const float4*)&As[k][ty*8];
            float4 a1 = *(const float4*)&As[k][ty*8+4];
            float4 b0 = *(const float4*)&Bs[k][tx*8];
            float4 b1 = *(const float4*)&Bs[k][tx*8+4];
            float ar[8] = {a0.x,a0.y,a0.z,a0.w,a1.x,a1.y,a1.z,a1.w};
            float br[8] = {b0.x,b0.y,b0.z,b0.w,b1.x,b1.y,b1.z,b1.w};
            #pragma unroll
            for (int i = 0; i < 8; i++)
                #pragma unroll
                for (int j = 0; j < 8; j++)
                    acc[i][j] += ar[i]*br[j];
        }
    }
    // epilogue
    #pragma unroll
    for (int i = 0; i < 8; i++) {
        int r = bm + ty*8 + i;
        float* Cr = C + (size_t)r*N + bn + tx*8;
        const float* br = bias + bn + tx*8;
        #pragma unroll
        for (int j = 0; j < 8; j++) {
            float v = acc[i][j] + br[j];
            if (doRelu) v = fmaxf(v, 0.f);
            Cr[j] = v;
        }
    }
}

// ---------------- sparse attention: only last query row is non-trivial ----------------
// One block per batch b. Computes per-head softmax over keys 0..510, writes
// o_last back into the v-section of g_qkv (row 511), and writes the
// head-averaged attention row into d_out's attns section for layer l.
__global__ __launch_bounds__(256)
void attn_kernel(float* __restrict__ out_attn, int l) {
    int b = blockIdx.x;
    int t = threadIdx.x;          // 256 threads
    __shared__ float sc[S_];
    __shared__ float arow[S_];
    __shared__ float qv[HD_];
    __shared__ float red[32];
    __shared__ float opart[8*HD_];
    arow[t] = 0.f; arow[t+256] = 0.f;
    const float scale = 0.17677669529663687f;   // 1/sqrt(32)
    float* qkv = g_qkv;
    size_t rowLast = (size_t)(b*S_ + (S_-1)) * QKV_LD;

    for (int h = 0; h < H_; h++) {
        __syncthreads();
        if (t < HD_) qv[t] = qkv[rowLast + h*HD_ + t];
        __syncthreads();

        // scores for k = t and k = t+256 (k=511 masked out)
        float s1, s2;
        {
            const float* kr = qkv + (size_t)(b*S_ + t)*QKV_LD + E_ + h*HD_;
            float a = 0.f;
            #pragma unroll
            for (int d = 0; d < HD_; d++) a += qv[d]*kr[d];
            s1 = a * scale;
            int k2 = t + 256;
            if (k2 != S_-1) {
                const float* kr2 = qkv + (size_t)(b*S_ + k2)*QKV_LD + E_ + h*HD_;
                float a2 = 0.f;
                #pragma unroll
                for (int d = 0; d < HD_; d++) a2 += qv[d]*kr2[d];
                s2 = a2 * scale;
            } else s2 = -1e30f;
        }
        float mx  = blockMax(fmaxf(s1, s2), red);
        float e1  = expf(s1 - mx);
        float e2  = (t + 256 == S_-1) ? 0.f : expf(s2 - mx);
        float sum = blockSum(e1 + e2, red);
        float inv = 1.0f / sum;
        float a1 = e1*inv, a2 = e2*inv;
        sc[t] = a1; sc[t+256] = a2;
        arow[t]     += a1 * 0.125f;
        arow[t+256] += a2 * 0.125f;
        __syncthreads();

        // o_last[d] = sum_{k<511} a_k * v[k][d]
        int g = t >> 5, d = t & 31;
        float oa = 0.f;
        for (int k = g; k < S_-1; k += 8)
            oa += sc[k] * qkv[(size_t)(b*S_ + k)*QKV_LD + 2*E_ + h*HD_ + d];
        opart[g*HD_ + d] = oa;
        __syncthreads();
        if (t < HD_) {
            float o = 0.f;
            #pragma unroll
            for (int gg = 0; gg < 8; gg++) o += opart[gg*HD_ + t];
            qkv[rowLast + 2*E_ + h*HD_ + t] = o;    // patch v row 511 -> o row 511
        }
    }
    __syncthreads();
    size_t base = ((size_t)(l*B_ + b)*S_ + (S_-1)) * S_;
    out_attn[base + t]       = arow[t];
    out_attn[base + t + 256] = arow[t+256];   // arow[511] stays exactly 0
}

// ---------------- residual + layernorm: x = LN(x + y)*g + b ----------------
__global__ __launch_bounds__(256)
void ln_kernel(const float* __restrict__ y,
               const float* __restrict__ g, const float* __restrict__ bb) {
    int m = blockIdx.x, e = threadIdx.x;
    __shared__ float red[32];
    size_t idx = (size_t)m*E_ + e;
    float v = g_x[idx] + y[idx];
    float mean = blockSum(v, red) * (1.0f/E_);
    float dv = v - mean;
    float var = blockSum(dv*dv, red) * (1.0f/E_);
    g_x[idx] = dv * rsqrtf(var + 1e-5f) * g[e] + bb[e];
}

// ---------------- decode head ----------------
__global__ __launch_bounds__(256)
void final_kernel(const float* __restrict__ decW, float* __restrict__ out) {
    int b = blockIdx.x, e = threadIdx.x;
    __shared__ float xs[E_];
    __shared__ float lg[C_];
    __shared__ float lse_s;
    float acc = 0.f;
    for (int s = 0; s < S_; s++)
        acc += fmaxf(g_x[((size_t)b*S_ + s)*E_ + e], 0.f);
    xs[e] = acc * (1.0f/S_);
    __syncthreads();
    if (e < C_) {
        float a = 0.f;
        for (int i = 0; i < E_; i++) a += xs[i]*decW[e*E_ + i];
        lg[e] = a;
    }
    __syncthreads();
    if (e == 0) {
        float m = -1e30f;
        for (int c = 0; c < C_; c++) m = fmaxf(m, lg[c]);
        float s = 0.f;
        for (int c = 0; c < C_; c++) s += expf(lg[c]-m);
        lse_s = m + logf(s);
    }
    __syncthreads();
    if (e < C_) out[b*C_ + e] = lg[e] - lse_s;
}

// ---------------- attns constant fill ----------------
__global__ void fill_zero(float4* __restrict__ p, int n4) {
    int i = blockIdx.x*blockDim.x + threadIdx.x;
    int stride = gridDim.x*blockDim.x;
    float4 z = make_float4(0.f,0.f,0.f,0.f);
    for (; i < n4; i += stride) p[i] = z;
}
__global__ void fill_ones(float* __restrict__ p) {
    int i = blockIdx.x*blockDim.x + threadIdx.x;
    if (i >= L_*B_*(S_-1)) return;
    int q  = i % (S_-1);
    int lb = i / (S_-1);
    p[((size_t)lb*S_ + q)*S_ + q] = 1.0f;
}

// ---------------- host ----------------
extern "C" void kernel_launch(void* const* d_in, const int* in_sizes, int n_in,
                              void* d_out, int out_size) {
    const float* src   = (const float*)d_in[0];
    const float* embW  = (const float*)d_in[1];
    const float* embb  = (const float*)d_in[2];
    const float* Wqkv  = (const float*)d_in[3];
    const float* bqkv  = (const float*)d_in[4];
    const float* Wo    = (const float*)d_in[5];
    const float* bo    = (const float*)d_in[6];
    const float* ln1g  = (const float*)d_in[7];
    const float* ln1b  = (const float*)d_in[8];
    const float* ln2g  = (const float*)d_in[9];
    const float* ln2b  = (const float*)d_in[10];
    const float* W1    = (const float*)d_in[11];
    const float* b1    = (const float*)d_in[12];
    const float* W2    = (const float*)d_in[13];
    const float* b2    = (const float*)d_in[14];
    const float* decW  = (const float*)d_in[15];
    float* out = (float*)d_out;
    float* out_attn = out + B_*C_;    // attns follow the [B,C] logits

    float *x, *qkv, *y, *h;
    cudaGetSymbolAddress((void**)&x,   g_x);
    cudaGetSymbolAddress((void**)&qkv, g_qkv);
    cudaGetSymbolAddress((void**)&y,   g_y);
    cudaGetSymbolAddress((void**)&h,   g_h);

    embed_kernel<<<M_, 256>>>(src, embW, embb);

    int n4 = (L_*B_*S_*S_) / 4;
    fill_zero<<<4096, 256>>>((float4*)out_attn, n4);
    fill_ones<<<(L_*B_*(S_-1) + 255)/256, 256>>>(out_attn);

    for (int l = 0; l < L_; l++) {
        // qkv = x @ Wqkv^T + bqkv            [16384,768]
        gemm_nt<<<dim3(3*E_/128, M_/128), 256>>>(
            x, E_, Wqkv + (size_t)l*3*E_*E_, bqkv + l*3*E_, qkv, 3*E_, E_, 0);
        // sparse attention (patches v row 511, writes attns last rows)
        attn_kernel<<<B_, 256>>>(out_attn, l);
        // y = o @ Wo^T + bo   (o is the v-view of qkv, lda=768)
        gemm_nt<<<dim3(E_/128, M_/128), 256>>>(
            qkv + 2*E_, QKV_LD, Wo + (size_t)l*E_*E_, bo + l*E_, y, E_, E_, 0);
        ln_kernel<<<M_, 256>>>(y, ln1g + l*E_, ln1b + l*E_);
        // h = relu(x @ W1^T + b1)            [16384,1024]
        gemm_nt<<<dim3(F_/128, M_/128), 256>>>(
            x, E_, W1 + (size_t)l*F_*E_, b1 + l*F_, h, F_, E_, 1);
        // y = h @ W2^T + b2                  [16384,256]
        gemm_nt<<<dim3(E_/128, M_/128), 256>>>(
            h, F_, W2 + (size_t)l*E_*F_, b2 + l*E_, y, E_, F_, 0);
        ln_kernel<<<M_, 256>>>(y, ln2g + l*E_, ln2b + l*E_);
    }

    final_kernel<<<B_, 256>>>(decW, out);
}

// round 3
// speedup vs baseline: 2.0462x; 2.0462x over previous
#include <cuda_runtime.h>
#include <cuda_bf16.h>
#include <math.h>
#include <stdint.h>

#define B_  32
#define S_  512
#define D_  9
#define E_  256
#define F_  1024
#define L_  4
#define C_  10
#define H_  8
#define HD_ 32
#define M_  (B_*S_)          // 16384 rows
#define QKV_LD 768

// ---------------- scratch (static __device__, no allocs) ----------------
__device__ float g_x  [M_*E_];        // activations fp32 (residual master)
__device__ float g_qkv[M_*3*E_];      // qkv fp32 (attn reads q,k,v)
__device__ float g_y  [M_*E_];        // proj/ffn2 out fp32

// bf16 hi/lo pre-split operand buffers
__device__ __nv_bfloat16 gx_h[M_*E_],    gx_l[M_*E_];
__device__ __nv_bfloat16 gq_h[M_*3*E_],  gq_l[M_*3*E_];
__device__ __nv_bfloat16 gh_h[M_*F_],    gh_l[M_*F_];
__device__ __nv_bfloat16 wq_h[L_*3*E_*E_], wq_l[L_*3*E_*E_];
__device__ __nv_bfloat16 wo_h[L_*E_*E_],   wo_l[L_*E_*E_];
__device__ __nv_bfloat16 w1_h[L_*F_*E_],   w1_l[L_*F_*E_];
__device__ __nv_bfloat16 w2_h[L_*E_*F_],   w2_l[L_*E_*F_];

// ================= PTX helpers (target-portable, NO tcgen05) =================
__device__ __forceinline__ uint32_t smem_u32(const void* p) {
    uint32_t a;
    asm("{ .reg .u64 t; cvta.to.shared.u64 t, %1; cvt.u32.u64 %0, t; }" : "=r"(a) : "l"(p));
    return a;
}
__device__ __forceinline__ void cp16(uint32_t dst, const void* src) {
    asm volatile("cp.async.cg.shared.global [%0], [%1], 16;\n" :: "r"(dst), "l"(src));
}
__device__ __forceinline__ void ldsm4(uint32_t* r, uint32_t addr) {
    asm volatile("ldmatrix.sync.aligned.m8n8.x4.shared.b16 {%0,%1,%2,%3}, [%4];"
        : "=r"(r[0]), "=r"(r[1]), "=r"(r[2]), "=r"(r[3]) : "r"(addr));
}
__device__ __forceinline__ void mma16816(float* d, const uint32_t* a, const uint32_t* b) {
    asm volatile("mma.sync.aligned.m16n8k16.row.col.f32.bf16.bf16.f32 "
        "{%0,%1,%2,%3}, {%4,%5,%6,%7}, {%8,%9}, {%0,%1,%2,%3};"
        : "+f"(d[0]), "+f"(d[1]), "+f"(d[2]), "+f"(d[3])
        : "r"(a[0]), "r"(a[1]), "r"(a[2]), "r"(a[3]), "r"(b[0]), "r"(b[1]));
}

// ================= GEMM: C[M,N] = A[M,K] @ B[N,K]^T + bias =================
// Pre-split bf16 hi/lo operands; fp32 accumulate via 3-pass HMMA.
// BM=BN=128, BK=64, 256 threads, warp grid 2x4, warp tile 64x32, 3 stages.
#define STAGES 3
#define STAGE_BYTES 65536
#define SMEM_REQ (STAGES*STAGE_BYTES + 1024)

__global__ __launch_bounds__(256, 1)
void gemm_mma(const __nv_bfloat16* __restrict__ Ah, const __nv_bfloat16* __restrict__ Al, int lda,
              const __nv_bfloat16* __restrict__ Bh, const __nv_bfloat16* __restrict__ Bl,
              const float* __restrict__ bias,
              float* __restrict__ C,
              __nv_bfloat16* __restrict__ Csh, __nv_bfloat16* __restrict__ Csl,
              int N, int K, int doRelu)
{
    extern __shared__ char dsm[];
    const uint32_t base = (smem_u32(dsm) + 1023u) & ~1023u;
    const int tid = threadIdx.x;
    const int lane = tid & 31, wid = tid >> 5;
    const int bm = blockIdx.y * 128, bn = blockIdx.x * 128;
    const int wm = wid >> 2, wn = wid & 3;

    const size_t lda2 = (size_t)lda * 2, ldb2 = (size_t)K * 2;
    const char* gAh = (const char*)Ah + (size_t)bm * lda2;
    const char* gAl = (const char*)Al + (size_t)bm * lda2;
    const char* gBh = (const char*)Bh + (size_t)bn * ldb2;
    const char* gBl = (const char*)Bl + (size_t)bn * ldb2;

    const int cc  = tid & 7;       // 16B chunk within 128B row
    const int rr0 = tid >> 3;      // row group

    auto load_stage = [&](int kt, int s) {
        uint32_t st = base + (uint32_t)s * STAGE_BYTES;
        size_t gk = (size_t)kt * 128 + (size_t)cc * 16;
        #pragma unroll
        for (int j = 0; j < 4; j++) {
            int r = rr0 + j * 32;
            uint32_t d = (uint32_t)(r * 128 + ((cc ^ (r & 7)) << 4));
            cp16(st + d,           gAh + (size_t)r * lda2 + gk);
            cp16(st + 16384 + d,   gAl + (size_t)r * lda2 + gk);
            cp16(st + 32768 + d,   gBh + (size_t)r * ldb2 + gk);
            cp16(st + 49152 + d,   gBl + (size_t)r * ldb2 + gk);
        }
        asm volatile("cp.async.commit_group;\n" ::: "memory");
    };

    // ldmatrix lane geometry (x4: matrices <- lane groups of 8)
    const int q = lane >> 3, r8 = lane & 7;
    int mRow[4], mSel[4];
    #pragma unroll
    for (int mt = 0; mt < 4; mt++) {
        int m = wm * 64 + mt * 16 + r8 + (q & 1) * 8;
        mRow[mt] = m * 128; mSel[mt] = m & 7;
    }
    const int aKH = q >> 1;
    int nRow[2], nSel[2];
    #pragma unroll
    for (int ng = 0; ng < 2; ng++) {
        int n = wn * 32 + ng * 16 + r8 + (q >> 1) * 8;
        nRow[ng] = n * 128; nSel[ng] = n & 7;
    }
    const int bKH = q & 1;

    float acc[4][4][4];
    #pragma unroll
    for (int a = 0; a < 4; a++)
        #pragma unroll
        for (int b = 0; b < 4; b++)
            #pragma unroll
            for (int c = 0; c < 4; c++) acc[a][b][c] = 0.f;

    const int nkt = K >> 6;
    int fetch = 0;
    for (; fetch < STAGES - 1 && fetch < nkt; fetch++) load_stage(fetch, fetch);

    for (int kt = 0; kt < nkt; kt++) {
        if (fetch < nkt) load_stage(fetch, fetch % STAGES);
        else asm volatile("cp.async.commit_group;\n" ::: "memory");
        fetch++;
        asm volatile("cp.async.wait_group %0;\n" :: "n"(STAGES - 1) : "memory");
        __syncthreads();

        const uint32_t sb = base + (uint32_t)(kt % STAGES) * STAGE_BYTES;
        #pragma unroll
        for (int ks = 0; ks < 4; ks++) {
            uint32_t ah[4][4], alr[4][4], bh[2][4], blr[2][4];
            #pragma unroll
            for (int mt = 0; mt < 4; mt++) {
                uint32_t off = (uint32_t)(mRow[mt] + (((ks * 2 + aKH) ^ mSel[mt]) << 4));
                ldsm4(ah[mt],  sb + off);
                ldsm4(alr[mt], sb + 16384 + off);
            }
            #pragma unroll
            for (int ng = 0; ng < 2; ng++) {
                uint32_t off = (uint32_t)(nRow[ng] + (((ks * 2 + bKH) ^ nSel[ng]) << 4));
                ldsm4(bh[ng],  sb + 32768 + off);
                ldsm4(blr[ng], sb + 49152 + off);
            }
            #pragma unroll
            for (int mt = 0; mt < 4; mt++)
                #pragma unroll
                for (int nt = 0; nt < 4; nt++) {
                    const uint32_t* ph = &bh[nt >> 1][(nt & 1) * 2];
                    const uint32_t* pl = &blr[nt >> 1][(nt & 1) * 2];
                    mma16816(acc[mt][nt], ah[mt],  ph);
                    mma16816(acc[mt][nt], alr[mt], ph);
                    mma16816(acc[mt][nt], ah[mt],  pl);
                }
        }
        __syncthreads();
    }

    // ---- epilogue ----
    const int mE = lane >> 2;
    const int nE = (lane & 3) << 1;
    #pragma unroll
    for (int mt = 0; mt < 4; mt++) {
        #pragma unroll
        for (int nt = 0; nt < 4; nt++) {
            int m0 = bm + wm * 64 + mt * 16 + mE;
            int n0 = bn + wn * 32 + nt * 8 + nE;
            float b0v = bias[n0], b1v = bias[n0 + 1];
            float v00 = acc[mt][nt][0] + b0v;
            float v01 = acc[mt][nt][1] + b1v;
            float v10 = acc[mt][nt][2] + b0v;
            float v11 = acc[mt][nt][3] + b1v;
            if (doRelu) {
                v00 = fmaxf(v00, 0.f); v01 = fmaxf(v01, 0.f);
                v10 = fmaxf(v10, 0.f); v11 = fmaxf(v11, 0.f);
            }
            size_t i0 = (size_t)m0 * N + n0;
            size_t i1 = (size_t)(m0 + 8) * N + n0;
            if (C) {
                *(float2*)(C + i0) = make_float2(v00, v01);
                *(float2*)(C + i1) = make_float2(v10, v11);
            }
            if (Csh) {
                __nv_bfloat16 h00 = __float2bfloat16(v00), h01 = __float2bfloat16(v01);
                __nv_bfloat16 h10 = __float2bfloat16(v10), h11 = __float2bfloat16(v11);
                *(__nv_bfloat162*)(Csh + i0) = __halves2bfloat162(h00, h01);
                *(__nv_bfloat162*)(Csh + i1) = __halves2bfloat162(h10, h11);
                *(__nv_bfloat162*)(Csl + i0) = __halves2bfloat162(
                    __float2bfloat16(v00 - __bfloat162float(h00)),
                    __float2bfloat16(v01 - __bfloat162float(h01)));
                *(__nv_bfloat162*)(Csl + i1) = __halves2bfloat162(
                    __float2bfloat16(v10 - __bfloat162float(h10)),
                    __float2bfloat16(v11 - __bfloat162float(h11)));
            }
        }
    }
}

// ---------------- hi/lo split (weights) ----------------
__global__ void split_kernel(const float* __restrict__ src,
                             __nv_bfloat16* __restrict__ h,
                             __nv_bfloat16* __restrict__ l, int n) {
    int i = blockIdx.x * blockDim.x + threadIdx.x;
    int stride = gridDim.x * blockDim.x;
    for (; i < n; i += stride) {
        float v = src[i];
        __nv_bfloat16 hh = __float2bfloat16(v);
        h[i] = hh;
        l[i] = __float2bfloat16(v - __bfloat162float(hh));
    }
}

// ---------------- reductions ----------------
__device__ __forceinline__ float warpSum(float v) {
    #pragma unroll
    for (int o = 16; o > 0; o >>= 1) v += __shfl_xor_sync(0xffffffffu, v, o);
    return v;
}
__device__ __forceinline__ float warpMax(float v) {
    #pragma unroll
    for (int o = 16; o > 0; o >>= 1) v = fmaxf(v, __shfl_xor_sync(0xffffffffu, v, o));
    return v;
}
__device__ float blockSum(float v, float* red) {
    int lane = threadIdx.x & 31, wid = threadIdx.x >> 5;
    v = warpSum(v);
    if (lane == 0) red[wid] = v;
    __syncthreads();
    if (wid == 0) {
        float x = (lane < 8) ? red[lane] : 0.f;
        x = warpSum(x);
        if (lane == 0) red[0] = x;
    }
    __syncthreads();
    float r = red[0];
    __syncthreads();
    return r;
}
__device__ float blockMax(float v, float* red) {
    int lane = threadIdx.x & 31, wid = threadIdx.x >> 5;
    v = warpMax(v);
    if (lane == 0) red[wid] = v;
    __syncthreads();
    if (wid == 0) {
        float x = (lane < 8) ? red[lane] : -1e30f;
        x = warpMax(x);
        if (lane == 0) red[0] = x;
    }
    __syncthreads();
    float r = red[0];
    __syncthreads();
    return r;
}

// ---------------- embed + posenc (writes fp32 + hi/lo) ----------------
__global__ void embed_kernel(const float* __restrict__ src,
                             const float* __restrict__ embW,
                             const float* __restrict__ embb) {
    int m = blockIdx.x;
    int e = threadIdx.x;
    __shared__ float sv[D_];
    if (e < D_) sv[e] = src[m*D_ + e];
    __syncthreads();
    float acc = 0.f;
    #pragma unroll
    for (int d = 0; d < D_; d++) acc += sv[d] * embW[e*D_ + d];
    acc = (acc + embb[e]) * 16.0f;
    int s  = m & (S_-1);
    int j2 = (e >> 1) * 2;
    const float c = -9.210340371976184f / (float)E_;
    float ang = (float)s * expf((float)j2 * c);
    float pe  = (e & 1) ? cosf(ang) : sinf(ang);
    float val = acc + pe;
    size_t idx = (size_t)m*E_ + e;
    g_x[idx] = val;
    __nv_bfloat16 hh = __float2bfloat16(val);
    gx_h[idx] = hh;
    gx_l[idx] = __float2bfloat16(val - __bfloat162float(hh));
}

// ---------------- sparse attention (last query row only) ----------------
__global__ __launch_bounds__(256)
void attn_kernel(float* __restrict__ out_attn, int l) {
    int b = blockIdx.x;
    int t = threadIdx.x;
    __shared__ float sc[S_];
    __shared__ float arow[S_];
    __shared__ float qv[HD_];
    __shared__ float red[32];
    __shared__ float opart[8*HD_];
    arow[t] = 0.f; arow[t+256] = 0.f;
    const float scale = 0.17677669529663687f;
    float* qkv = g_qkv;
    size_t rowLast = (size_t)(b*S_ + (S_-1)) * QKV_LD;

    for (int h = 0; h < H_; h++) {
        __syncthreads();
        if (t < HD_) qv[t] = qkv[rowLast + h*HD_ + t];
        __syncthreads();
        float s1, s2;
        {
            const float* kr = qkv + (size_t)(b*S_ + t)*QKV_LD + E_ + h*HD_;
            float a = 0.f;
            #pragma unroll
            for (int d = 0; d < HD_; d++) a += qv[d]*kr[d];
            s1 = a * scale;
            int k2 = t + 256;
            if (k2 != S_-1) {
                const float* kr2 = qkv + (size_t)(b*S_ + k2)*QKV_LD + E_ + h*HD_;
                float a2 = 0.f;
                #pragma unroll
                for (int d = 0; d < HD_; d++) a2 += qv[d]*kr2[d];
                s2 = a2 * scale;
            } else s2 = -1e30f;
        }
        float mx  = blockMax(fmaxf(s1, s2), red);
        float e1  = expf(s1 - mx);
        float e2  = (t + 256 == S_-1) ? 0.f : expf(s2 - mx);
        float sum = blockSum(e1 + e2, red);
        float inv = 1.0f / sum;
        float a1 = e1*inv, a2 = e2*inv;
        sc[t] = a1; sc[t+256] = a2;
        arow[t]     += a1 * 0.125f;
        arow[t+256] += a2 * 0.125f;
        __syncthreads();
        int g = t >> 5, d = t & 31;
        float oa = 0.f;
        for (int k = g; k < S_-1; k += 8)
            oa += sc[k] * qkv[(size_t)(b*S_ + k)*QKV_LD + 2*E_ + h*HD_ + d];
        opart[g*HD_ + d] = oa;
        __syncthreads();
        if (t < HD_) {
            float o = 0.f;
            #pragma unroll
            for (int gg = 0; gg < 8; gg++) o += opart[gg*HD_ + t];
            size_t oi = rowLast + 2*E_ + h*HD_ + t;
            qkv[oi] = o;                       // fp32 patch
            __nv_bfloat16 hh = __float2bfloat16(o);
            gq_h[oi] = hh;                     // bf16 hi/lo patch (proj input)
            gq_l[oi] = __float2bfloat16(o - __bfloat162float(hh));
        }
    }
    __syncthreads();
    size_t basei = ((size_t)(l*B_ + b)*S_ + (S_-1)) * S_;
    out_attn[basei + t]       = arow[t];
    out_attn[basei + t + 256] = arow[t+256];
}

// ---------------- residual + layernorm (writes fp32 + hi/lo) ----------------
__global__ __launch_bounds__(256)
void ln_kernel(const float* __restrict__ y,
               const float* __restrict__ g, const float* __restrict__ bb) {
    int m = blockIdx.x, e = threadIdx.x;
    __shared__ float red[32];
    size_t idx = (size_t)m*E_ + e;
    float v = g_x[idx] + y[idx];
    float mean = blockSum(v, red) * (1.0f/E_);
    float dv = v - mean;
    float var = blockSum(dv*dv, red) * (1.0f/E_);
    float res = dv * rsqrtf(var + 1e-5f) * g[e] + bb[e];
    g_x[idx] = res;
    __nv_bfloat16 hh = __float2bfloat16(res);
    gx_h[idx] = hh;
    gx_l[idx] = __float2bfloat16(res - __bfloat162float(hh));
}

// ---------------- decode head ----------------
__global__ __launch_bounds__(256)
void final_kernel(const float* __restrict__ decW, float* __restrict__ out) {
    int b = blockIdx.x, e = threadIdx.x;
    __shared__ float xs[E_];
    __shared__ float lg[C_];
    __shared__ float lse_s;
    float acc = 0.f;
    for (int s = 0; s < S_; s++)
        acc += fmaxf(g_x[((size_t)b*S_ + s)*E_ + e], 0.f);
    xs[e] = acc * (1.0f/S_);
    __syncthreads();
    if (e < C_) {
        float a = 0.f;
        for (int i = 0; i < E_; i++) a += xs[i]*decW[e*E_ + i];
        lg[e] = a;
    }
    __syncthreads();
    if (e == 0) {
        float m = -1e30f;
        for (int c = 0; c < C_; c++) m = fmaxf(m, lg[c]);
        float s = 0.f;
        for (int c = 0; c < C_; c++) s += expf(lg[c]-m);
        lse_s = m + logf(s);
    }
    __syncthreads();
    if (e < C_) out[b*C_ + e] = lg[e] - lse_s;
}

// ---------------- attns constant fill ----------------
__global__ void fill_zero(float4* __restrict__ p, int n4) {
    int i = blockIdx.x*blockDim.x + threadIdx.x;
    int stride = gridDim.x*blockDim.x;
    float4 z = make_float4(0.f,0.f,0.f,0.f);
    for (; i < n4; i += stride) p[i] = z;
}
__global__ void fill_ones(float* __restrict__ p) {
    int i = blockIdx.x*blockDim.x + threadIdx.x;
    if (i >= L_*B_*(S_-1)) return;
    int q  = i % (S_-1);
    int lb = i / (S_-1);
    p[((size_t)lb*S_ + q)*S_ + q] = 1.0f;
}

// ---------------- host ----------------
extern "C" void kernel_launch(void* const* d_in, const int* in_sizes, int n_in,
                              void* d_out, int out_size) {
    const float* src   = (const float*)d_in[0];
    const float* embW  = (const float*)d_in[1];
    const float* embb  = (const float*)d_in[2];
    const float* Wqkv  = (const float*)d_in[3];
    const float* bqkv  = (const float*)d_in[4];
    const float* Wo    = (const float*)d_in[5];
    const float* bo    = (const float*)d_in[6];
    const float* ln1g  = (const float*)d_in[7];
    const float* ln1b  = (const float*)d_in[8];
    const float* ln2g  = (const float*)d_in[9];
    const float* ln2b  = (const float*)d_in[10];
    const float* W1    = (const float*)d_in[11];
    const float* b1    = (const float*)d_in[12];
    const float* W2    = (const float*)d_in[13];
    const float* b2    = (const float*)d_in[14];
    const float* decW  = (const float*)d_in[15];
    float* out = (float*)d_out;
    float* out_attn = out + B_*C_;

    float *qkv, *y;
    __nv_bfloat16 *xh, *xl, *qh, *ql, *hh, *hl;
    __nv_bfloat16 *wqh, *wql, *woh, *wol, *w1h, *w1l, *w2h, *w2l;
    cudaGetSymbolAddress((void**)&qkv, g_qkv);
    cudaGetSymbolAddress((void**)&y,   g_y);
    cudaGetSymbolAddress((void**)&xh, gx_h);  cudaGetSymbolAddress((void**)&xl, gx_l);
    cudaGetSymbolAddress((void**)&qh, gq_h);  cudaGetSymbolAddress((void**)&ql, gq_l);
    cudaGetSymbolAddress((void**)&hh, gh_h);  cudaGetSymbolAddress((void**)&hl, gh_l);
    cudaGetSymbolAddress((void**)&wqh, wq_h); cudaGetSymbolAddress((void**)&wql, wq_l);
    cudaGetSymbolAddress((void**)&woh, wo_h); cudaGetSymbolAddress((void**)&wol, wo_l);
    cudaGetSymbolAddress((void**)&w1h, w1_h); cudaGetSymbolAddress((void**)&w1l, w1_l);
    cudaGetSymbolAddress((void**)&w2h, w2_h); cudaGetSymbolAddress((void**)&w2l, w2_l);

    cudaFuncSetAttribute(gemm_mma, cudaFuncAttributeMaxDynamicSharedMemorySize, SMEM_REQ);

    // weight splits (cheap, every call -> deterministic)
    split_kernel<<<1024, 256>>>(Wqkv, wqh, wql, L_*3*E_*E_);
    split_kernel<<<512,  256>>>(Wo,   woh, wol, L_*E_*E_);
    split_kernel<<<1024, 256>>>(W1,   w1h, w1l, L_*F_*E_);
    split_kernel<<<1024, 256>>>(W2,   w2h, w2l, L_*E_*F_);

    embed_kernel<<<M_, 256>>>(src, embW, embb);

    int n4 = (L_*B_*S_*S_) / 4;
    fill_zero<<<4096, 256>>>((float4*)out_attn, n4);
    fill_ones<<<(L_*B_*(S_-1) + 255)/256, 256>>>(out_attn);

    for (int l = 0; l < L_; l++) {
        // qkv = x @ Wqkv^T + bqkv  [16384,768] fp32 + hi/lo split-out
        gemm_mma<<<dim3(6, 128), 256, SMEM_REQ>>>(
            xh, xl, E_, wqh + (size_t)l*3*E_*E_, wql + (size_t)l*3*E_*E_,
            bqkv + l*3*E_, qkv, qh, ql, 3*E_, E_, 0);
        attn_kernel<<<B_, 256>>>(out_attn, l);
        // y = o @ Wo^T + bo   (o = v-view of split qkv, lda=768)
        gemm_mma<<<dim3(2, 128), 256, SMEM_REQ>>>(
            qh + 2*E_, ql + 2*E_, QKV_LD, woh + (size_t)l*E_*E_, wol + (size_t)l*E_*E_,
            bo + l*E_, y, (__nv_bfloat16*)0, (__nv_bfloat16*)0, E_, E_, 0);
        ln_kernel<<<M_, 256>>>(y, ln1g + l*E_, ln1b + l*E_);
        // h = relu(x @ W1^T + b1)  -> bf16 hi/lo only
        gemm_mma<<<dim3(8, 128), 256, SMEM_REQ>>>(
            xh, xl, E_, w1h + (size_t)l*F_*E_, w1l + (size_t)l*F_*E_,
            b1 + l*F_, (float*)0, hh, hl, F_, E_, 1);
        // y = h @ W2^T + b2
        gemm_mma<<<dim3(2, 128), 256, SMEM_REQ>>>(
            hh, hl, F_, w2h + (size_t)l*E_*F_, w2l + (size_t)l*E_*F_,
            b2 + l*E_, y, (__nv_bfloat16*)0, (__nv_bfloat16*)0, E_, F_, 0);
        ln_kernel<<<M_, 256>>>(y, ln2g + l*E_, ln2b + l*E_);
    }

    final_kernel<<<B_, 256>>>(decW, out);
}

// round 4
// speedup vs baseline: 2.5561x; 1.2492x over previous
#include <cuda_runtime.h>
#include <cuda_bf16.h>
#include <cuda_fp16.h>
#include <math.h>
#include <stdint.h>

#define B_  32
#define S_  512
#define D_  9
#define E_  256
#define F_  1024
#define L_  4
#define C_  10
#define H_  8
#define HD_ 32
#define M_  (B_*S_)          // 16384 rows
#define KV_LD 512

// ---------------- scratch (static __device__, no allocs) ----------------
__device__ float g_x [M_*E_];         // activations fp32 (residual master)
__device__ float g_kv[M_*KV_LD];      // fp32 k(0..255), v(256..511) per row
__device__ float g_y [M_*E_];         // proj/ffn2 out fp32

// fp16 operand buffers (A-side needs hi/lo; weights hi only)
__device__ __half gx_h[M_*E_],  gx_l[M_*E_];
__device__ __half gk_h[M_*KV_LD], gk_l[M_*KV_LD];
__device__ __half gh_h[M_*F_],  gh_l[M_*F_];
__device__ __half wq_h[L_*3*E_*E_];
__device__ __half wo_h[L_*E_*E_];
__device__ __half w1_h[L_*F_*E_];
__device__ __half w2_h[L_*E_*F_];

// ================= PTX helpers (target-portable) =================
__device__ __forceinline__ uint32_t smem_u32(const void* p) {
    uint32_t a;
    asm("{ .reg .u64 t; cvta.to.shared.u64 t, %1; cvt.u32.u64 %0, t; }" : "=r"(a) : "l"(p));
    return a;
}
__device__ __forceinline__ void cp16(uint32_t dst, const void* src) {
    asm volatile("cp.async.cg.shared.global [%0], [%1], 16;\n" :: "r"(dst), "l"(src));
}
__device__ __forceinline__ void ldsm4(uint32_t* r, uint32_t addr) {
    asm volatile("ldmatrix.sync.aligned.m8n8.x4.shared.b16 {%0,%1,%2,%3}, [%4];"
        : "=r"(r[0]), "=r"(r[1]), "=r"(r[2]), "=r"(r[3]) : "r"(addr));
}
__device__ __forceinline__ void mma16816(float* d, const uint32_t* a, const uint32_t* b) {
    asm volatile("mma.sync.aligned.m16n8k16.row.col.f32.f16.f16.f32 "
        "{%0,%1,%2,%3}, {%4,%5,%6,%7}, {%8,%9}, {%0,%1,%2,%3};"
        : "+f"(d[0]), "+f"(d[1]), "+f"(d[2]), "+f"(d[3])
        : "r"(a[0]), "r"(a[1]), "r"(a[2]), "r"(a[3]), "r"(b[0]), "r"(b[1]));
}

// ================= GEMM: C[M,N] = A[M,K] @ B[N,K]^T + bias =================
// A = Ah + Al (fp16 hi/lo), B = Bh (fp16). 2 MMA passes (A·Bh).
// BM=BN=128, BK=64, 256 threads, warp grid 2x4, warp tile 64x32, 2 stages.
#define STAGES 2
#define STAGE_BYTES 49152          // Ah 16K | Al 16K | Bh 16K
#define SMEM_REQ (STAGES*STAGE_BYTES + 1024)

__global__ __launch_bounds__(256, 2)
void gemm_mma(const __half* __restrict__ Ah, const __half* __restrict__ Al, int lda,
              const __half* __restrict__ Bh,
              const float* __restrict__ bias,
              float* __restrict__ C,
              __half* __restrict__ Csh, __half* __restrict__ Csl,
              int N, int K, int doRelu)
{
    extern __shared__ char dsm[];
    const uint32_t base = (smem_u32(dsm) + 1023u) & ~1023u;
    const int tid = threadIdx.x;
    const int lane = tid & 31, wid = tid >> 5;
    const int bm = blockIdx.y * 128, bn = blockIdx.x * 128;
    const int wm = wid >> 2, wn = wid & 3;

    const size_t lda2 = (size_t)lda * 2, ldb2 = (size_t)K * 2;
    const char* gAh = (const char*)Ah + (size_t)bm * lda2;
    const char* gAl = (const char*)Al + (size_t)bm * lda2;
    const char* gBh = (const char*)Bh + (size_t)bn * ldb2;

    const int cc  = tid & 7;       // 16B chunk within 128B row
    const int rr0 = tid >> 3;      // row group (0..31)

    auto load_stage = [&](int kt, int s) {
        uint32_t st = base + (uint32_t)s * STAGE_BYTES;
        size_t gk = (size_t)kt * 128 + (size_t)cc * 16;
        #pragma unroll
        for (int j = 0; j < 4; j++) {
            int r = rr0 + j * 32;
            uint32_t d = (uint32_t)(r * 128 + ((cc ^ (r & 7)) << 4));
            cp16(st + d,           gAh + (size_t)r * lda2 + gk);
            cp16(st + 16384 + d,   gAl + (size_t)r * lda2 + gk);
            cp16(st + 32768 + d,   gBh + (size_t)r * ldb2 + gk);
        }
        asm volatile("cp.async.commit_group;\n" ::: "memory");
    };

    // ldmatrix lane geometry
    const int q = lane >> 3, r8 = lane & 7;
    int mRow[4], mSel[4];
    #pragma unroll
    for (int mt = 0; mt < 4; mt++) {
        int m = wm * 64 + mt * 16 + r8 + (q & 1) * 8;
        mRow[mt] = m * 128; mSel[mt] = m & 7;
    }
    const int aKH = q >> 1;
    int nRow[2], nSel[2];
    #pragma unroll
    for (int ng = 0; ng < 2; ng++) {
        int n = wn * 32 + ng * 16 + r8 + (q >> 1) * 8;
        nRow[ng] = n * 128; nSel[ng] = n & 7;
    }
    const int bKH = q & 1;

    float acc[4][4][4];
    #pragma unroll
    for (int a = 0; a < 4; a++)
        #pragma unroll
        for (int b = 0; b < 4; b++)
            #pragma unroll
            for (int c = 0; c < 4; c++) acc[a][b][c] = 0.f;

    const int nkt = K >> 6;
    load_stage(0, 0);

    for (int kt = 0; kt < nkt; kt++) {
        if (kt + 1 < nkt) load_stage(kt + 1, (kt + 1) & 1);
        else asm volatile("cp.async.commit_group;\n" ::: "memory");
        asm volatile("cp.async.wait_group 1;\n" ::: "memory");
        __syncthreads();

        const uint32_t sb = base + (uint32_t)(kt & 1) * STAGE_BYTES;
        #pragma unroll
        for (int ks = 0; ks < 4; ks++) {
            uint32_t ah[4][4], alr[4][4], bh[2][4];
            #pragma unroll
            for (int mt = 0; mt < 4; mt++) {
                uint32_t off = (uint32_t)(mRow[mt] + (((ks * 2 + aKH) ^ mSel[mt]) << 4));
                ldsm4(ah[mt],  sb + off);
                ldsm4(alr[mt], sb + 16384 + off);
            }
            #pragma unroll
            for (int ng = 0; ng < 2; ng++) {
                uint32_t off = (uint32_t)(nRow[ng] + (((ks * 2 + bKH) ^ nSel[ng]) << 4));
                ldsm4(bh[ng], sb + 32768 + off);
            }
            #pragma unroll
            for (int mt = 0; mt < 4; mt++)
                #pragma unroll
                for (int nt = 0; nt < 4; nt++) {
                    const uint32_t* ph = &bh[nt >> 1][(nt & 1) * 2];
                    mma16816(acc[mt][nt], ah[mt],  ph);
                    mma16816(acc[mt][nt], alr[mt], ph);
                }
        }
        __syncthreads();
    }

    // ---- epilogue ----
    const int mE = lane >> 2;
    const int nE = (lane & 3) << 1;
    #pragma unroll
    for (int mt = 0; mt < 4; mt++) {
        #pragma unroll
        for (int nt = 0; nt < 4; nt++) {
            int m0 = bm + wm * 64 + mt * 16 + mE;
            int n0 = bn + wn * 32 + nt * 8 + nE;
            float b0v = bias[n0], b1v = bias[n0 + 1];
            float v00 = acc[mt][nt][0] + b0v;
            float v01 = acc[mt][nt][1] + b1v;
            float v10 = acc[mt][nt][2] + b0v;
            float v11 = acc[mt][nt][3] + b1v;
            if (doRelu) {
                v00 = fmaxf(v00, 0.f); v01 = fmaxf(v01, 0.f);
                v10 = fmaxf(v10, 0.f); v11 = fmaxf(v11, 0.f);
            }
            size_t i0 = (size_t)m0 * N + n0;
            size_t i1 = (size_t)(m0 + 8) * N + n0;
            if (C) {
                *(float2*)(C + i0) = make_float2(v00, v01);
                *(float2*)(C + i1) = make_float2(v10, v11);
            }
            if (Csh) {
                __half h00 = __float2half(v00), h01 = __float2half(v01);
                __half h10 = __float2half(v10), h11 = __float2half(v11);
                *(__half2*)(Csh + i0) = __halves2half2(h00, h01);
                *(__half2*)(Csh + i1) = __halves2half2(h10, h11);
                *(__half2*)(Csl + i0) = __halves2half2(
                    __float2half(v00 - __half2float(h00)),
                    __float2half(v01 - __half2float(h01)));
                *(__half2*)(Csl + i1) = __halves2half2(
                    __float2half(v10 - __half2float(h10)),
                    __float2half(v11 - __half2float(h11)));
            }
        }
    }
}

// ---------------- weight -> fp16 hi split ----------------
__global__ void split1_kernel(const float* __restrict__ src,
                              __half* __restrict__ h, int n) {
    int i = blockIdx.x * blockDim.x + threadIdx.x;
    int stride = gridDim.x * blockDim.x;
    for (; i < n; i += stride) h[i] = __float2half(src[i]);
}

// ---------------- reductions ----------------
__device__ __forceinline__ float warpSum(float v) {
    #pragma unroll
    for (int o = 16; o > 0; o >>= 1) v += __shfl_xor_sync(0xffffffffu, v, o);
    return v;
}
__device__ __forceinline__ float warpMax(float v) {
    #pragma unroll
    for (int o = 16; o > 0; o >>= 1) v = fmaxf(v, __shfl_xor_sync(0xffffffffu, v, o));
    return v;
}
__device__ float blockSum(float v, float* red) {
    int lane = threadIdx.x & 31, wid = threadIdx.x >> 5;
    v = warpSum(v);
    if (lane == 0) red[wid] = v;
    __syncthreads();
    if (wid == 0) {
        float x = (lane < 8) ? red[lane] : 0.f;
        x = warpSum(x);
        if (lane == 0) red[0] = x;
    }
    __syncthreads();
    float r = red[0];
    __syncthreads();
    return r;
}
__device__ float blockMax(float v, float* red) {
    int lane = threadIdx.x & 31, wid = threadIdx.x >> 5;
    v = warpMax(v);
    if (lane == 0) red[wid] = v;
    __syncthreads();
    if (wid == 0) {
        float x = (lane < 8) ? red[lane] : -1e30f;
        x = warpMax(x);
        if (lane == 0) red[0] = x;
    }
    __syncthreads();
    float r = red[0];
    __syncthreads();
    return r;
}

// ---------------- embed + posenc (writes fp32 + hi/lo) ----------------
__global__ void embed_kernel(const float* __restrict__ src,
                             const float* __restrict__ embW,
                             const float* __restrict__ embb) {
    int m = blockIdx.x;
    int e = threadIdx.x;
    __shared__ float sv[D_];
    if (e < D_) sv[e] = src[m*D_ + e];
    __syncthreads();
    float acc = 0.f;
    #pragma unroll
    for (int d = 0; d < D_; d++) acc += sv[d] * embW[e*D_ + d];
    acc = (acc + embb[e]) * 16.0f;
    int s  = m & (S_-1);
    int j2 = (e >> 1) * 2;
    const float c = -9.210340371976184f / (float)E_;
    float ang = (float)s * expf((float)j2 * c);
    float pe  = (e & 1) ? cosf(ang) : sinf(ang);
    float val = acc + pe;
    size_t idx = (size_t)m*E_ + e;
    g_x[idx] = val;
    __half hh = __float2half(val);
    gx_h[idx] = hh;
    gx_l[idx] = __float2half(val - __half2float(hh));
}

// ---------------- sparse attention (last query row only) ----------------
// Computes q_last in-kernel from x and Wq; k,v read from g_kv (stride 512).
__global__ __launch_bounds__(256)
void attn_kernel(float* __restrict__ out_attn, int l,
                 const float* __restrict__ Wq, const float* __restrict__ bq) {
    int b = blockIdx.x;
    int t = threadIdx.x;
    __shared__ float sc[S_];
    __shared__ float arow[S_];
    __shared__ float xlast[E_];
    __shared__ float q_sh[E_];
    __shared__ float red[32];
    __shared__ float opart[8*HD_];
    arow[t] = 0.f; arow[t+256] = 0.f;
    const float scale = 0.17677669529663687f;
    float* kv = g_kv;
    size_t rowLast = (size_t)(b*S_ + (S_-1)) * KV_LD;

    // q_last = x[last] @ Wq^T + bq
    xlast[t] = g_x[(size_t)(b*S_ + (S_-1))*E_ + t];
    __syncthreads();
    {
        float a = 0.f;
        const float* wr = Wq + (size_t)t * E_;
        #pragma unroll 8
        for (int i = 0; i < E_; i++) a += xlast[i] * wr[i];
        q_sh[t] = a + bq[t];
    }
    __syncthreads();

    for (int h = 0; h < H_; h++) {
        const float* qv = q_sh + h*HD_;
        float s1, s2;
        {
            const float* kr = kv + (size_t)(b*S_ + t)*KV_LD + h*HD_;
            float a = 0.f;
            #pragma unroll
            for (int d = 0; d < HD_; d++) a += qv[d]*kr[d];
            s1 = a * scale;
            int k2 = t + 256;
            if (k2 != S_-1) {
                const float* kr2 = kv + (size_t)(b*S_ + k2)*KV_LD + h*HD_;
                float a2 = 0.f;
                #pragma unroll
                for (int d = 0; d < HD_; d++) a2 += qv[d]*kr2[d];
                s2 = a2 * scale;
            } else s2 = -1e30f;
        }
        float mx  = blockMax(fmaxf(s1, s2), red);
        float e1  = expf(s1 - mx);
        float e2  = (t + 256 == S_-1) ? 0.f : expf(s2 - mx);
        float sum = blockSum(e1 + e2, red);
        float inv = 1.0f / sum;
        float a1 = e1*inv, a2 = e2*inv;
        sc[t] = a1; sc[t+256] = a2;
        arow[t]     += a1 * 0.125f;
        arow[t+256] += a2 * 0.125f;
        __syncthreads();
        int g = t >> 5, d = t & 31;
        float oa = 0.f;
        for (int k = g; k < S_-1; k += 8)
            oa += sc[k] * kv[(size_t)(b*S_ + k)*KV_LD + E_ + h*HD_ + d];
        opart[g*HD_ + d] = oa;
        __syncthreads();
        if (t < HD_) {
            float o = 0.f;
            #pragma unroll
            for (int gg = 0; gg < 8; gg++) o += opart[gg*HD_ + t];
            size_t oi = rowLast + E_ + h*HD_ + t;
            __half hh = __float2half(o);
            gk_h[oi] = hh;                 // patch v-view hi/lo (proj input)
            gk_l[oi] = __float2half(o - __half2float(hh));
        }
        __syncthreads();
    }
    size_t basei = ((size_t)(l*B_ + b)*S_ + (S_-1)) * S_;
    out_attn[basei + t]       = arow[t];
    out_attn[basei + t + 256] = arow[t+256];
}

// ---------------- residual + layernorm (writes fp32 + hi/lo) ----------------
__global__ __launch_bounds__(256)
void ln_kernel(const float* __restrict__ y,
               const float* __restrict__ g, const float* __restrict__ bb) {
    int m = blockIdx.x, e = threadIdx.x;
    __shared__ float red[32];
    size_t idx = (size_t)m*E_ + e;
    float v = g_x[idx] + y[idx];
    float mean = blockSum(v, red) * (1.0f/E_);
    float dv = v - mean;
    float var = blockSum(dv*dv, red) * (1.0f/E_);
    float res = dv * rsqrtf(var + 1e-5f) * g[e] + bb[e];
    g_x[idx] = res;
    __half hh = __float2half(res);
    gx_h[idx] = hh;
    gx_l[idx] = __float2half(res - __half2float(hh));
}

// ---------------- decode head ----------------
__global__ __launch_bounds__(256)
void final_kernel(const float* __restrict__ decW, float* __restrict__ out) {
    int b = blockIdx.x, e = threadIdx.x;
    __shared__ float xs[E_];
    __shared__ float lg[C_];
    __shared__ float lse_s;
    float acc = 0.f;
    for (int s = 0; s < S_; s++)
        acc += fmaxf(g_x[((size_t)b*S_ + s)*E_ + e], 0.f);
    xs[e] = acc * (1.0f/S_);
    __syncthreads();
    if (e < C_) {
        float a = 0.f;
        for (int i = 0; i < E_; i++) a += xs[i]*decW[e*E_ + i];
        lg[e] = a;
    }
    __syncthreads();
    if (e == 0) {
        float m = -1e30f;
        for (int c = 0; c < C_; c++) m = fmaxf(m, lg[c]);
        float s = 0.f;
        for (int c = 0; c < C_; c++) s += expf(lg[c]-m);
        lse_s = m + logf(s);
    }
    __syncthreads();
    if (e < C_) out[b*C_ + e] = lg[e] - lse_s;
}

// ---------------- attns constant fill ----------------
__global__ void fill_zero(float4* __restrict__ p, int n4) {
    int i = blockIdx.x*blockDim.x + threadIdx.x;
    int stride = gridDim.x*blockDim.x;
    float4 z = make_float4(0.f,0.f,0.f,0.f);
    for (; i < n4; i += stride) p[i] = z;
}
__global__ void fill_ones(float* __restrict__ p) {
    int i = blockIdx.x*blockDim.x + threadIdx.x;
    if (i >= L_*B_*(S_-1)) return;
    int q  = i % (S_-1);
    int lb = i / (S_-1);
    p[((size_t)lb*S_ + q)*S_ + q] = 1.0f;
}

// ---------------- host ----------------
extern "C" void kernel_launch(void* const* d_in, const int* in_sizes, int n_in,
                              void* d_out, int out_size) {
    const float* src   = (const float*)d_in[0];
    const float* embW  = (const float*)d_in[1];
    const float* embb  = (const float*)d_in[2];
    const float* Wqkv  = (const float*)d_in[3];
    const float* bqkv  = (const float*)d_in[4];
    const float* Wo    = (const float*)d_in[5];
    const float* bo    = (const float*)d_in[6];
    const float* ln1g  = (const float*)d_in[7];
    const float* ln1b  = (const float*)d_in[8];
    const float* ln2g  = (const float*)d_in[9];
    const float* ln2b  = (const float*)d_in[10];
    const float* W1    = (const float*)d_in[11];
    const float* b1    = (const float*)d_in[12];
    const float* W2    = (const float*)d_in[13];
    const float* b2    = (const float*)d_in[14];
    const float* decW  = (const float*)d_in[15];
    float* out = (float*)d_out;
    float* out_attn = out + B_*C_;

    float *kv, *y;
    __half *xh, *xl, *kh, *kl, *hh, *hl;
    __half *wqh, *woh, *w1h, *w2h;
    cudaGetSymbolAddress((void**)&kv, g_kv);
    cudaGetSymbolAddress((void**)&y,  g_y);
    cudaGetSymbolAddress((void**)&xh, gx_h);  cudaGetSymbolAddress((void**)&xl, gx_l);
    cudaGetSymbolAddress((void**)&kh, gk_h);  cudaGetSymbolAddress((void**)&kl, gk_l);
    cudaGetSymbolAddress((void**)&hh, gh_h);  cudaGetSymbolAddress((void**)&hl, gh_l);
    cudaGetSymbolAddress((void**)&wqh, wq_h);
    cudaGetSymbolAddress((void**)&woh, wo_h);
    cudaGetSymbolAddress((void**)&w1h, w1_h);
    cudaGetSymbolAddress((void**)&w2h, w2_h);

    cudaFuncSetAttribute(gemm_mma, cudaFuncAttributeMaxDynamicSharedMemorySize, SMEM_REQ);

    // weight fp16 conversions (cheap, every call -> deterministic)
    split1_kernel<<<1024, 256>>>(Wqkv, wqh, L_*3*E_*E_);
    split1_kernel<<<512,  256>>>(Wo,   woh, L_*E_*E_);
    split1_kernel<<<1024, 256>>>(W1,   w1h, L_*F_*E_);
    split1_kernel<<<1024, 256>>>(W2,   w2h, L_*E_*F_);

    embed_kernel<<<M_, 256>>>(src, embW, embb);

    int n4 = (L_*B_*S_*S_) / 4;
    fill_zero<<<4096, 256>>>((float4*)out_attn, n4);
    fill_ones<<<(L_*B_*(S_-1) + 255)/256, 256>>>(out_attn);

    for (int l = 0; l < L_; l++) {
        const size_t wq_off = (size_t)l*3*E_*E_;
        // kv = x @ [Wk;Wv]^T + b   [16384,512] fp32 + fp16 hi/lo
        gemm_mma<<<dim3(4, 128), 256, SMEM_REQ>>>(
            xh, xl, E_, wqh + wq_off + (size_t)E_*E_,
            bqkv + l*3*E_ + E_, kv, kh, kl, KV_LD, E_, 0);
        // sparse attention: q_last computed in-kernel; patches v last row hi/lo
        attn_kernel<<<B_, 256>>>(out_attn, l, Wqkv + wq_off, bqkv + l*3*E_);
        // y = o @ Wo^T + bo   (o = v-view of kv splits, lda=512)
        gemm_mma<<<dim3(2, 128), 256, SMEM_REQ>>>(
            kh + E_, kl + E_, KV_LD, woh + (size_t)l*E_*E_,
            bo + l*E_, y, (__half*)0, (__half*)0, E_, E_, 0);
        ln_kernel<<<M_, 256>>>(y, ln1g + l*E_, ln1b + l*E_);
        // h = relu(x @ W1^T + b1)  -> fp16 hi/lo only
        gemm_mma<<<dim3(8, 128), 256, SMEM_REQ>>>(
            xh, xl, E_, w1h + (size_t)l*F_*E_,
            b1 + l*F_, (float*)0, hh, hl, F_, E_, 1);
        // y = h @ W2^T + b2
        gemm_mma<<<dim3(2, 128), 256, SMEM_REQ>>>(
            hh, hl, F_, w2h + (size_t)l*E_*F_,
            b2 + l*E_, y, (__half*)0, (__half*)0, E_, F_, 0);
        ln_kernel<<<M_, 256>>>(y, ln2g + l*E_, ln2b + l*E_);
    }

    final_kernel<<<B_, 256>>>(decW, out);
}

// round 5
// speedup vs baseline: 3.3010x; 1.2914x over previous
#include <cuda_runtime.h>
#include <cuda_fp16.h>
#include <math.h>
#include <stdint.h>

#define B_  32
#define S_  512
#define D_  9
#define E_  256
#define F_  1024
#define L_  4
#define C_  10
#define H_  8
#define HD_ 32
#define M_  (B_*S_)          // 16384 rows
#define KV_LD 512

// ---------------- scratch (static __device__, no allocs) ----------------
__device__ float g_x [M_*E_];         // activations fp32 (residual master)
__device__ float g_y [M_*E_];         // proj/ffn2 out fp32

// fp16 operand buffers
__device__ __half gx_h[M_*E_];        // x fp16
__device__ __half gk_h[M_*KV_LD];     // k(0..255), v->o(256..511) fp16
__device__ __half gh_h[M_*F_];        // ffn hidden fp16
__device__ __half wq_h[L_*3*E_*E_];
__device__ __half wo_h[L_*E_*E_];
__device__ __half w1_h[L_*F_*E_];
__device__ __half w2_h[L_*E_*F_];

// ================= PTX helpers (target-portable) =================
__device__ __forceinline__ uint32_t smem_u32(const void* p) {
    uint32_t a;
    asm("{ .reg .u64 t; cvta.to.shared.u64 t, %1; cvt.u32.u64 %0, t; }" : "=r"(a) : "l"(p));
    return a;
}
__device__ __forceinline__ void cp16(uint32_t dst, const void* src) {
    asm volatile("cp.async.cg.shared.global [%0], [%1], 16;\n" :: "r"(dst), "l"(src));
}
__device__ __forceinline__ void ldsm4(uint32_t* r, uint32_t addr) {
    asm volatile("ldmatrix.sync.aligned.m8n8.x4.shared.b16 {%0,%1,%2,%3}, [%4];"
        : "=r"(r[0]), "=r"(r[1]), "=r"(r[2]), "=r"(r[3]) : "r"(addr));
}
__device__ __forceinline__ void mma16816(float* d, const uint32_t* a, const uint32_t* b) {
    asm volatile("mma.sync.aligned.m16n8k16.row.col.f32.f16.f16.f32 "
        "{%0,%1,%2,%3}, {%4,%5,%6,%7}, {%8,%9}, {%0,%1,%2,%3};"
        : "+f"(d[0]), "+f"(d[1]), "+f"(d[2]), "+f"(d[3])
        : "r"(a[0]), "r"(a[1]), "r"(a[2]), "r"(a[3]), "r"(b[0]), "r"(b[1]));
}

// ================= GEMM: C[M,N] = A[M,K] @ B[N,K]^T + bias =================
// Pure fp16 operands, fp32 accumulate, single pass.
// BM=BN=128, BK=64, 256 threads, warp grid 2x4, warp tile 64x32, 2 stages.
#define STAGES 2
#define STAGE_BYTES 32768          // Ah 16K | Bh 16K
#define SMEM_REQ (STAGES*STAGE_BYTES + 1024)

__global__ __launch_bounds__(256, 2)
void gemm_mma(const __half* __restrict__ Ah, int lda,
              const __half* __restrict__ Bh,
              const float* __restrict__ bias,
              float* __restrict__ C,
              __half* __restrict__ Csh,
              int N, int K, int doRelu)
{
    extern __shared__ char dsm[];
    const uint32_t base = (smem_u32(dsm) + 1023u) & ~1023u;
    const int tid = threadIdx.x;
    const int lane = tid & 31, wid = tid >> 5;
    const int bm = blockIdx.y * 128, bn = blockIdx.x * 128;
    const int wm = wid >> 2, wn = wid & 3;

    const size_t lda2 = (size_t)lda * 2, ldb2 = (size_t)K * 2;
    const char* gAh = (const char*)Ah + (size_t)bm * lda2;
    const char* gBh = (const char*)Bh + (size_t)bn * ldb2;

    const int cc  = tid & 7;       // 16B chunk within 128B row
    const int rr0 = tid >> 3;      // row group (0..31)

    auto load_stage = [&](int kt, int s) {
        uint32_t st = base + (uint32_t)s * STAGE_BYTES;
        size_t gk = (size_t)kt * 128 + (size_t)cc * 16;
        #pragma unroll
        for (int j = 0; j < 4; j++) {
            int r = rr0 + j * 32;
            uint32_t d = (uint32_t)(r * 128 + ((cc ^ (r & 7)) << 4));
            cp16(st + d,           gAh + (size_t)r * lda2 + gk);
            cp16(st + 16384 + d,   gBh + (size_t)r * ldb2 + gk);
        }
        asm volatile("cp.async.commit_group;\n" ::: "memory");
    };

    // ldmatrix lane geometry
    const int q = lane >> 3, r8 = lane & 7;
    int mRow[4], mSel[4];
    #pragma unroll
    for (int mt = 0; mt < 4; mt++) {
        int m = wm * 64 + mt * 16 + r8 + (q & 1) * 8;
        mRow[mt] = m * 128; mSel[mt] = m & 7;
    }
    const int aKH = q >> 1;
    int nRow[2], nSel[2];
    #pragma unroll
    for (int ng = 0; ng < 2; ng++) {
        int n = wn * 32 + ng * 16 + r8 + (q >> 1) * 8;
        nRow[ng] = n * 128; nSel[ng] = n & 7;
    }
    const int bKH = q & 1;

    float acc[4][4][4];
    #pragma unroll
    for (int a = 0; a < 4; a++)
        #pragma unroll
        for (int b = 0; b < 4; b++)
            #pragma unroll
            for (int c = 0; c < 4; c++) acc[a][b][c] = 0.f;

    const int nkt = K >> 6;
    load_stage(0, 0);

    for (int kt = 0; kt < nkt; kt++) {
        if (kt + 1 < nkt) load_stage(kt + 1, (kt + 1) & 1);
        else asm volatile("cp.async.commit_group;\n" ::: "memory");
        asm volatile("cp.async.wait_group 1;\n" ::: "memory");
        __syncthreads();

        const uint32_t sb = base + (uint32_t)(kt & 1) * STAGE_BYTES;
        #pragma unroll
        for (int ks = 0; ks < 4; ks++) {
            uint32_t ah[4][4], bh[2][4];
            #pragma unroll
            for (int mt = 0; mt < 4; mt++) {
                uint32_t off = (uint32_t)(mRow[mt] + (((ks * 2 + aKH) ^ mSel[mt]) << 4));
                ldsm4(ah[mt], sb + off);
            }
            #pragma unroll
            for (int ng = 0; ng < 2; ng++) {
                uint32_t off = (uint32_t)(nRow[ng] + (((ks * 2 + bKH) ^ nSel[ng]) << 4));
                ldsm4(bh[ng], sb + 16384 + off);
            }
            #pragma unroll
            for (int mt = 0; mt < 4; mt++)
                #pragma unroll
                for (int nt = 0; nt < 4; nt++)
                    mma16816(acc[mt][nt], ah[mt], &bh[nt >> 1][(nt & 1) * 2]);
        }
        __syncthreads();
    }

    // ---- epilogue ----
    const int mE = lane >> 2;
    const int nE = (lane & 3) << 1;
    #pragma unroll
    for (int mt = 0; mt < 4; mt++) {
        #pragma unroll
        for (int nt = 0; nt < 4; nt++) {
            int m0 = bm + wm * 64 + mt * 16 + mE;
            int n0 = bn + wn * 32 + nt * 8 + nE;
            float b0v = bias[n0], b1v = bias[n0 + 1];
            float v00 = acc[mt][nt][0] + b0v;
            float v01 = acc[mt][nt][1] + b1v;
            float v10 = acc[mt][nt][2] + b0v;
            float v11 = acc[mt][nt][3] + b1v;
            if (doRelu) {
                v00 = fmaxf(v00, 0.f); v01 = fmaxf(v01, 0.f);
                v10 = fmaxf(v10, 0.f); v11 = fmaxf(v11, 0.f);
            }
            size_t i0 = (size_t)m0 * N + n0;
            size_t i1 = (size_t)(m0 + 8) * N + n0;
            if (C) {
                *(float2*)(C + i0) = make_float2(v00, v01);
                *(float2*)(C + i1) = make_float2(v10, v11);
            }
            if (Csh) {
                *(__half2*)(Csh + i0) = __halves2half2(__float2half(v00), __float2half(v01));
                *(__half2*)(Csh + i1) = __halves2half2(__float2half(v10), __float2half(v11));
            }
        }
    }
}

// ---------------- weight -> fp16 ----------------
__global__ void split1_kernel(const float* __restrict__ src,
                              __half* __restrict__ h, int n) {
    int i = blockIdx.x * blockDim.x + threadIdx.x;
    int stride = gridDim.x * blockDim.x;
    for (; i < n; i += stride) h[i] = __float2half(src[i]);
}

// ---------------- reductions ----------------
__device__ __forceinline__ float warpSum(float v) {
    #pragma unroll
    for (int o = 16; o > 0; o >>= 1) v += __shfl_xor_sync(0xffffffffu, v, o);
    return v;
}
__device__ __forceinline__ float warpMax(float v) {
    #pragma unroll
    for (int o = 16; o > 0; o >>= 1) v = fmaxf(v, __shfl_xor_sync(0xffffffffu, v, o));
    return v;
}
__device__ float blockSum(float v, float* red) {
    int lane = threadIdx.x & 31, wid = threadIdx.x >> 5;
    v = warpSum(v);
    if (lane == 0) red[wid] = v;
    __syncthreads();
    if (wid == 0) {
        float x = (lane < 8) ? red[lane] : 0.f;
        x = warpSum(x);
        if (lane == 0) red[0] = x;
    }
    __syncthreads();
    float r = red[0];
    __syncthreads();
    return r;
}
__device__ float blockMax(float v, float* red) {
    int lane = threadIdx.x & 31, wid = threadIdx.x >> 5;
    v = warpMax(v);
    if (lane == 0) red[wid] = v;
    __syncthreads();
    if (wid == 0) {
        float x = (lane < 8) ? red[lane] : -1e30f;
        x = warpMax(x);
        if (lane == 0) red[0] = x;
    }
    __syncthreads();
    float r = red[0];
    __syncthreads();
    return r;
}

// ---------------- embed + posenc (fp32 + fp16) ----------------
__global__ void embed_kernel(const float* __restrict__ src,
                             const float* __restrict__ embW,
                             const float* __restrict__ embb) {
    int m = blockIdx.x;
    int e = threadIdx.x;
    __shared__ float sv[D_];
    if (e < D_) sv[e] = src[m*D_ + e];
    __syncthreads();
    float acc = 0.f;
    #pragma unroll
    for (int d = 0; d < D_; d++) acc += sv[d] * embW[e*D_ + d];
    acc = (acc + embb[e]) * 16.0f;
    int s  = m & (S_-1);
    int j2 = (e >> 1) * 2;
    const float c = -9.210340371976184f / (float)E_;
    float ang = (float)s * expf((float)j2 * c);
    float pe  = (e & 1) ? cosf(ang) : sinf(ang);
    float val = acc + pe;
    size_t idx = (size_t)m*E_ + e;
    g_x[idx] = val;
    gx_h[idx] = __float2half(val);
}

// ---------------- sparse attention (last query row only) ----------------
// q_last computed from fp32 x/Wq; k,v read fp16 from gk_h (stride 512).
__global__ __launch_bounds__(256)
void attn_kernel(float* __restrict__ out_attn, int l,
                 const float* __restrict__ Wq, const float* __restrict__ bq) {
    int b = blockIdx.x;
    int t = threadIdx.x;
    __shared__ float sc[S_];
    __shared__ float arow[S_];
    __shared__ float xlast[E_];
    __shared__ float q_sh[E_];
    __shared__ float red[32];
    __shared__ float opart[8*HD_];
    arow[t] = 0.f; arow[t+256] = 0.f;
    const float scale = 0.17677669529663687f;
    const __half* kv = gk_h;
    size_t rowLast = (size_t)(b*S_ + (S_-1)) * KV_LD;

    // q_last = x[last] @ Wq^T + bq
    xlast[t] = g_x[(size_t)(b*S_ + (S_-1))*E_ + t];
    __syncthreads();
    {
        float a = 0.f;
        const float* wr = Wq + (size_t)t * E_;
        #pragma unroll 8
        for (int i = 0; i < E_; i++) a += xlast[i] * wr[i];
        q_sh[t] = a + bq[t];
    }
    __syncthreads();

    for (int h = 0; h < H_; h++) {
        const float* qv = q_sh + h*HD_;
        float s1, s2;
        {
            const __half* kr = kv + (size_t)(b*S_ + t)*KV_LD + h*HD_;
            float a = 0.f;
            #pragma unroll
            for (int d = 0; d < HD_; d++) a += qv[d]*__half2float(kr[d]);
            s1 = a * scale;
            int k2 = t + 256;
            if (k2 != S_-1) {
                const __half* kr2 = kv + (size_t)(b*S_ + k2)*KV_LD + h*HD_;
                float a2 = 0.f;
                #pragma unroll
                for (int d = 0; d < HD_; d++) a2 += qv[d]*__half2float(kr2[d]);
                s2 = a2 * scale;
            } else s2 = -1e30f;
        }
        float mx  = blockMax(fmaxf(s1, s2), red);
        float e1  = expf(s1 - mx);
        float e2  = (t + 256 == S_-1) ? 0.f : expf(s2 - mx);
        float sum = blockSum(e1 + e2, red);
        float inv = 1.0f / sum;
        float a1 = e1*inv, a2 = e2*inv;
        sc[t] = a1; sc[t+256] = a2;
        arow[t]     += a1 * 0.125f;
        arow[t+256] += a2 * 0.125f;
        __syncthreads();
        int g = t >> 5, d = t & 31;
        float oa = 0.f;
        for (int k = g; k < S_-1; k += 8)
            oa += sc[k] * __half2float(kv[(size_t)(b*S_ + k)*KV_LD + E_ + h*HD_ + d]);
        opart[g*HD_ + d] = oa;
        __syncthreads();
        if (t < HD_) {
            float o = 0.f;
            #pragma unroll
            for (int gg = 0; gg < 8; gg++) o += opart[gg*HD_ + t];
            gk_h[rowLast + E_ + h*HD_ + t] = __float2half(o);  // patch v->o
        }
        __syncthreads();
    }
    size_t basei = ((size_t)(l*B_ + b)*S_ + (S_-1)) * S_;
    out_attn[basei + t]       = arow[t];
    out_attn[basei + t + 256] = arow[t+256];
}

// ---------------- residual + layernorm (fp32 + fp16) ----------------
__global__ __launch_bounds__(256)
void ln_kernel(const float* __restrict__ y,
               const float* __restrict__ g, const float* __restrict__ bb) {
    int m = blockIdx.x, e = threadIdx.x;
    __shared__ float red[32];
    size_t idx = (size_t)m*E_ + e;
    float v = g_x[idx] + y[idx];
    float mean = blockSum(v, red) * (1.0f/E_);
    float dv = v - mean;
    float var = blockSum(dv*dv, red) * (1.0f/E_);
    float res = dv * rsqrtf(var + 1e-5f) * g[e] + bb[e];
    g_x[idx] = res;
    gx_h[idx] = __float2half(res);
}

// ---------------- decode head ----------------
__global__ __launch_bounds__(256)
void final_kernel(const float* __restrict__ decW, float* __restrict__ out) {
    int b = blockIdx.x, e = threadIdx.x;
    __shared__ float xs[E_];
    __shared__ float lg[C_];
    __shared__ float lse_s;
    float acc = 0.f;
    for (int s = 0; s < S_; s++)
        acc += fmaxf(g_x[((size_t)b*S_ + s)*E_ + e], 0.f);
    xs[e] = acc * (1.0f/S_);
    __syncthreads();
    if (e < C_) {
        float a = 0.f;
        for (int i = 0; i < E_; i++) a += xs[i]*decW[e*E_ + i];
        lg[e] = a;
    }
    __syncthreads();
    if (e == 0) {
        float m = -1e30f;
        for (int c = 0; c < C_; c++) m = fmaxf(m, lg[c]);
        float s = 0.f;
        for (int c = 0; c < C_; c++) s += expf(lg[c]-m);
        lse_s = m + logf(s);
    }
    __syncthreads();
    if (e < C_) out[b*C_ + e] = lg[e] - lse_s;
}

// ---------------- attns constant fill ----------------
__global__ void fill_zero(float4* __restrict__ p, int n4) {
    int i = blockIdx.x*blockDim.x + threadIdx.x;
    int stride = gridDim.x*blockDim.x;
    float4 z = make_float4(0.f,0.f,0.f,0.f);
    for (; i < n4; i += stride) p[i] = z;
}
__global__ void fill_ones(float* __restrict__ p) {
    int i = blockIdx.x*blockDim.x + threadIdx.x;
    if (i >= L_*B_*(S_-1)) return;
    int q  = i % (S_-1);
    int lb = i / (S_-1);
    p[((size_t)lb*S_ + q)*S_ + q] = 1.0f;
}

// ---------------- host ----------------
extern "C" void kernel_launch(void* const* d_in, const int* in_sizes, int n_in,
                              void* d_out, int out_size) {
    const float* src   = (const float*)d_in[0];
    const float* embW  = (const float*)d_in[1];
    const float* embb  = (const float*)d_in[2];
    const float* Wqkv  = (const float*)d_in[3];
    const float* bqkv  = (const float*)d_in[4];
    const float* Wo    = (const float*)d_in[5];
    const float* bo    = (const float*)d_in[6];
    const float* ln1g  = (const float*)d_in[7];
    const float* ln1b  = (const float*)d_in[8];
    const float* ln2g  = (const float*)d_in[9];
    const float* ln2b  = (const float*)d_in[10];
    const float* W1    = (const float*)d_in[11];
    const float* b1    = (const float*)d_in[12];
    const float* W2    = (const float*)d_in[13];
    const float* b2    = (const float*)d_in[14];
    const float* decW  = (const float*)d_in[15];
    float* out = (float*)d_out;
    float* out_attn = out + B_*C_;

    float *y;
    __half *xh, *kh, *hh;
    __half *wqh, *woh, *w1h, *w2h;
    cudaGetSymbolAddress((void**)&y,  g_y);
    cudaGetSymbolAddress((void**)&xh, gx_h);
    cudaGetSymbolAddress((void**)&kh, gk_h);
    cudaGetSymbolAddress((void**)&hh, gh_h);
    cudaGetSymbolAddress((void**)&wqh, wq_h);
    cudaGetSymbolAddress((void**)&woh, wo_h);
    cudaGetSymbolAddress((void**)&w1h, w1_h);
    cudaGetSymbolAddress((void**)&w2h, w2_h);

    cudaFuncSetAttribute(gemm_mma, cudaFuncAttributeMaxDynamicSharedMemorySize, SMEM_REQ);

    split1_kernel<<<1024, 256>>>(Wqkv, wqh, L_*3*E_*E_);
    split1_kernel<<<512,  256>>>(Wo,   woh, L_*E_*E_);
    split1_kernel<<<1024, 256>>>(W1,   w1h, L_*F_*E_);
    split1_kernel<<<1024, 256>>>(W2,   w2h, L_*E_*F_);

    embed_kernel<<<M_, 256>>>(src, embW, embb);

    int n4 = (L_*B_*S_*S_) / 4;
    fill_zero<<<4096, 256>>>((float4*)out_attn, n4);
    fill_ones<<<(L_*B_*(S_-1) + 255)/256, 256>>>(out_attn);

    for (int l = 0; l < L_; l++) {
        const size_t wq_off = (size_t)l*3*E_*E_;
        // kv = x @ [Wk;Wv]^T + b   [16384,512] -> fp16 only
        gemm_mma<<<dim3(4, 128), 256, SMEM_REQ>>>(
            xh, E_, wqh + wq_off + (size_t)E_*E_,
            bqkv + l*3*E_ + E_, (float*)0, kh, KV_LD, E_, 0);
        // sparse attention: q_last in-kernel; patches v last row fp16
        attn_kernel<<<B_, 256>>>(out_attn, l, Wqkv + wq_off, bqkv + l*3*E_);
        // y = o @ Wo^T + bo  (o = v-view of kh, lda=512) -> fp32
        gemm_mma<<<dim3(2, 128), 256, SMEM_REQ>>>(
            kh + E_, KV_LD, woh + (size_t)l*E_*E_,
            bo + l*E_, y, (__half*)0, E_, E_, 0);
        ln_kernel<<<M_, 256>>>(y, ln1g + l*E_, ln1b + l*E_);
        // h = relu(x @ W1^T + b1) -> fp16 only
        gemm_mma<<<dim3(8, 128), 256, SMEM_REQ>>>(
            xh, E_, w1h + (size_t)l*F_*E_,
            b1 + l*F_, (float*)0, hh, F_, E_, 1);
        // y = h @ W2^T + b2 -> fp32
        gemm_mma<<<dim3(2, 128), 256, SMEM_REQ>>>(
            hh, F_, w2h + (size_t)l*E_*F_,
            b2 + l*E_, y, (__half*)0, E_, F_, 0);
        ln_kernel<<<M_, 256>>>(y, ln2g + l*E_, ln2b + l*E_);
    }

    final_kernel<<<B_, 256>>>(decW, out);
}